// round 10
// baseline (speedup 1.0000x reference)
#include <cuda_runtime.h>
#include <cstdint>
#include <cstddef>

#define TT   512
#define BB   128
#define EE   512
#define HH   512
#define G5   2560
#define LEE  512
#define EPSV 1e-5f
#define NBLK 128      // LSTM persistent blocks (1 per SM, co-resident)
#define CK   64       // LSTM k-chunk

// ------------------------- static device scratch ---------------------------
__device__ float    g_pre[(size_t)TT * BB * G5];   // [t*128+b][2560]
__device__ float    g_hbuf[3][BB * HH];            // rotating hidden (SLOT space)
__device__ float    g_xsel[BB * HH];               // outs[label_len[b], b] (real b)
__device__ float    g_z0[BB * LEE];
__device__ unsigned g_syncv[4];                    // 4-way split barrier counters
__device__ int      g_slot2b[BB];                  // slot (=rank) -> real batch
__device__ int      g_Lslot[BB];                   // slot -> label_len (ascending)
__device__ int      g_maxL;

// ------------------- packed f32x2 FMA (sm_103a FFMA2) ----------------------
union F2U { float2 f; unsigned long long u; };
struct F4v { F2U lo, hi; };   // 16B = two f32x2 lanes
__device__ __forceinline__ void ffma2(F2U& acc, F2U a, F2U b) {
    asm("fma.rn.f32x2 %0, %1, %2, %0;" : "+l"(acc.u) : "l"(a.u), "l"(b.u));
}
__device__ __forceinline__ float sgm(float x) { return 1.f / (1.f + __expf(-x)); }
__device__ __forceinline__ float tanh_fast(float x) {
    return 1.f - 2.f / (1.f + __expf(2.f * x));
}

// ------------------ profiling-alignment no-op launches ---------------------
__global__ void k_nop() {}

// --------------------------- init + length sort ----------------------------
__global__ void k_init(const int* __restrict__ llen) {
    int i = blockIdx.x * blockDim.x + threadIdx.x;
    if (i < BB * HH) g_hbuf[0][i] = 0.f;
    if (blockIdx.x == 0) {
        if (threadIdx.x < 4) g_syncv[threadIdx.x] = 0u;
        if (threadIdx.x < BB) {
            int b  = threadIdx.x;
            int Lb = llen[b];
            int r = 0, mx = 0;
            #pragma unroll 4
            for (int j = 0; j < BB; j++) {
                int Lj = llen[j];
                r  += (Lj < Lb) || (Lj == Lb && j < b);
                mx  = max(mx, Lj);
            }
            g_slot2b[r] = b;      // slot == stable rank (ascending L)
            g_Lslot[r]  = Lb;
            if (threadIdx.x == 0) g_maxL = mx;
        }
    }
}

// ---------------- K1: pre = gather(embed) @ i2h_w^T + i2h_b ----------------
// M = T*B (m = t*128+b), N = 2560, K = 512. BM=BN=128, BK=16, 256 thr, 8x8/thr.
// Double-buffered SMEM: ONE __syncthreads per 16-k tile (32 total).
__global__ __launch_bounds__(256, 2)
void k_pre(const int* __restrict__ label, const float* __restrict__ embed_w,
           const float* __restrict__ i2h_w, const float* __restrict__ i2h_b)
{
    __shared__ __align__(16) float As[2][16][128];
    __shared__ __align__(16) float Ws[2][16][128];

    const int tid = threadIdx.x;
    const int tx = tid & 15, ty = tid >> 4;
    const int n0 = blockIdx.x * 128, m0 = blockIdx.y * 128;
    const int ml = tid >> 1, lk = (tid & 1) * 8;

    const int m = m0 + ml, t_ = m >> 7, b_ = m & 127;
    const float* arow = embed_w + (size_t)label[b_ * TT + t_] * EE;
    const float* wrow = i2h_w + (size_t)(n0 + ml) * EE;

    F2U acc[8][4];
    #pragma unroll
    for (int i = 0; i < 8; i++)
        #pragma unroll
        for (int j = 0; j < 4; j++) acc[i][j].u = 0ull;

    float4 ra0 = *(const float4*)(arow + lk);
    float4 ra1 = *(const float4*)(arow + lk + 4);
    float4 rw0 = *(const float4*)(wrow + lk);
    float4 rw1 = *(const float4*)(wrow + lk + 4);

    #pragma unroll 1
    for (int ko = 0; ko < EE / 16; ++ko) {
        const int buf = ko & 1;
        As[buf][lk + 0][ml] = ra0.x; As[buf][lk + 1][ml] = ra0.y;
        As[buf][lk + 2][ml] = ra0.z; As[buf][lk + 3][ml] = ra0.w;
        As[buf][lk + 4][ml] = ra1.x; As[buf][lk + 5][ml] = ra1.y;
        As[buf][lk + 6][ml] = ra1.z; As[buf][lk + 7][ml] = ra1.w;
        Ws[buf][lk + 0][ml] = rw0.x; Ws[buf][lk + 1][ml] = rw0.y;
        Ws[buf][lk + 2][ml] = rw0.z; Ws[buf][lk + 3][ml] = rw0.w;
        Ws[buf][lk + 4][ml] = rw1.x; Ws[buf][lk + 5][ml] = rw1.y;
        Ws[buf][lk + 6][ml] = rw1.z; Ws[buf][lk + 7][ml] = rw1.w;
        __syncthreads();              // single sync per tile (double buffer)
        if (ko + 1 < EE / 16) {
            const int kb = (ko + 1) * 16 + lk;
            ra0 = *(const float4*)(arow + kb);
            ra1 = *(const float4*)(arow + kb + 4);
            rw0 = *(const float4*)(wrow + kb);
            rw1 = *(const float4*)(wrow + kb + 4);
        }
        #pragma unroll
        for (int k = 0; k < 16; ++k) {
            float4 aA = *(const float4*)&As[buf][k][ty * 8];       // broadcast
            float4 aB = *(const float4*)&As[buf][k][ty * 8 + 4];   // broadcast
            F4v bA = *(const F4v*)&Ws[buf][k][tx * 4];             // conflict-free
            F4v bB = *(const F4v*)&Ws[buf][k][64 + tx * 4];        // conflict-free
            float av[8] = {aA.x, aA.y, aA.z, aA.w, aB.x, aB.y, aB.z, aB.w};
            #pragma unroll
            for (int i = 0; i < 8; i++) {
                F2U ad; ad.f.x = av[i]; ad.f.y = av[i];
                ffma2(acc[i][0], ad, bA.lo);
                ffma2(acc[i][1], ad, bA.hi);
                ffma2(acc[i][2], ad, bB.lo);
                ffma2(acc[i][3], ad, bB.hi);
            }
        }
    }

    const float4 bi0 = *(const float4*)(i2h_b + n0 + tx * 4);
    const float4 bi1 = *(const float4*)(i2h_b + n0 + 64 + tx * 4);
    #pragma unroll
    for (int i = 0; i < 8; i++) {
        const int mrow = m0 + ty * 8 + i;
        float* op = g_pre + (size_t)mrow * G5 + n0 + tx * 4;
        float4 o0, o1;
        o0.x = acc[i][0].f.x + bi0.x; o0.y = acc[i][0].f.y + bi0.y;
        o0.z = acc[i][1].f.x + bi0.z; o0.w = acc[i][1].f.y + bi0.w;
        o1.x = acc[i][2].f.x + bi1.x; o1.y = acc[i][2].f.y + bi1.y;
        o1.z = acc[i][3].f.x + bi1.z; o1.w = acc[i][3].f.y + bi1.w;
        *(float4*)op        = o0;
        *(float4*)(op + 64) = o1;
    }
}

// ------------------------- K2: persistent LSTM -----------------------------
// 128 blocks x 256 threads. Block owns 4 hidden units.
// Thread (up = tid>>7, bp = tid&127) computes 2 units (ju0 = blk*4+up*2, +1)
// for ONE slot bp; slot == length-sorted rank, so each warp spans 32
// consecutive ranks and retires coherently once t exceeds its max L.
// The stager row (ls = tid&127) equals the compute slot -> same predicate.
__global__ __launch_bounds__(256, 1)
void k_lstm(const float* __restrict__ h2h_w, const float* __restrict__ h2h_b)
{
    extern __shared__ float sm[];
    float* w_s = sm;                 // [20][512]  rows r = g*4 + u
    float* h_s = sm + 20 * HH;       // [2][16][128][4] double-buffered chunk

    const int tid = threadIdx.x;
    const int up  = tid >> 7;        // unit-pair select (0/1)
    const int bp  = tid & 127;       // slot (== rank)
    const int blk = blockIdx.x;
    const int ju0 = blk * 4 + up * 2;

    // resident weights: 20 rows x 512
    for (int i = tid; i < 20 * HH / 4; i += 256) {
        int r = i / (HH / 4), k4 = i % (HH / 4);
        int g = r >> 2, u = r & 3;
        *(float4*)(w_s + r * HH + k4 * 4) =
            *(const float4*)(h2h_w + (size_t)(g * HH + blk * 4 + u) * HH + k4 * 4);
    }

    float2 bias2[5];
    #pragma unroll
    for (int g = 0; g < 5; g++)
        bias2[g] = *(const float2*)(h2h_b + g * HH + ju0);

    const int b    = g_slot2b[bp];
    const int myL  = g_Lslot[bp];
    const int maxT = g_maxL;

    float c0 = 0.f, c1 = 0.f;
    __syncthreads();

    #pragma unroll 1
    for (int t = 0; t <= maxT; ++t) {
        const float* hcur = g_hbuf[t % 3];
        float*       hnxt = g_hbuf[(t + 1) % 3];
        const bool   act  = (t <= myL);   // warp-coherent in 32-rank spans

        F2U acc[10];                      // [gate][unit]
        #pragma unroll
        for (int g = 0; g < 10; g++) acc[g].u = 0ull;

        float2 pvv[5];
        #pragma unroll
        for (int g = 0; g < 5; g++) pvv[g] = make_float2(0.f, 0.f);

        // prefetch chunk 0 of own h row (L2 path: peers' writes) + pre-acts
        float4 rg[8];
        if (act) {
            const float* src = hcur + bp * HH + up * 32;
            #pragma unroll
            for (int q = 0; q < 8; q++) rg[q] = __ldcg((const float4*)(src + q * 4));
            #pragma unroll
            for (int g = 0; g < 5; g++)
                pvv[g] = *(const float2*)(g_pre + ((size_t)t * BB + b) * G5
                                          + g * HH + ju0);
        }

        #pragma unroll 1
        for (int ch = 0; ch < HH / CK; ++ch) {
            float* hb = h_s + (ch & 1) * (16 * BB * 4);
            if (act) {
                #pragma unroll
                for (int q = 0; q < 8; q++)   // h_s[k4 = up*8+q][bp][0..3]
                    *(float4*)(hb + ((up * 8 + q) * BB + bp) * 4) = rg[q];
            }
            __syncthreads();                  // single sync (double buffer)
            if (act && ch + 1 < HH / CK) {
                const float* src = hcur + bp * HH + (ch + 1) * CK + up * 32;
                #pragma unroll
                for (int q = 0; q < 8; q++) rg[q] = __ldcg((const float4*)(src + q * 4));
            }
            if (act) {
                const F4v* hp = (const F4v*)hb;
                const float* wb = w_s + ch * CK;
                #pragma unroll
                for (int kq = 0; kq < CK / 4; ++kq) {
                    F4v h = hp[kq * BB + bp];            // conflict-free
                    #pragma unroll
                    for (int g = 0; g < 5; g++) {
                        F4v w0 = *(const F4v*)(wb + (size_t)(g * 4 + up * 2) * HH
                                               + kq * 4);       // broadcast
                        F4v w1 = *(const F4v*)(wb + (size_t)(g * 4 + up * 2 + 1) * HH
                                               + kq * 4);       // broadcast
                        ffma2(acc[g * 2 + 0], h.lo, w0.lo);
                        ffma2(acc[g * 2 + 0], h.hi, w0.hi);
                        ffma2(acc[g * 2 + 1], h.lo, w1.lo);
                        ffma2(acc[g * 2 + 1], h.hi, w1.hi);
                    }
                }
            }
        }

        if (act) {
            float s0[5], s1[5];
            #pragma unroll
            for (int g = 0; g < 5; g++) {
                s0[g] = acc[g * 2 + 0].f.x + acc[g * 2 + 0].f.y + bias2[g].x + pvv[g].x;
                s1[g] = acc[g * 2 + 1].f.x + acc[g * 2 + 1].f.y + bias2[g].y + pvv[g].y;
            }
            float i0 = sgm(s0[0]), f0 = sgm(s0[1]), o0 = sgm(s0[2]);
            float i1 = sgm(s1[0]), f1 = sgm(s1[1]), o1 = sgm(s1[2]);
            float a0 = fmaxf(s0[3], s0[4]), a1 = fmaxf(s1[3], s1[4]);
            c0 = f0 * c0 + i0 * a0;
            c1 = f1 * c1 + i1 * a1;
            float nh0 = o0 * tanh_fast(c0);
            float nh1 = o1 * tanh_fast(c1);
            *(float2*)(hnxt + bp * HH + ju0) = make_float2(nh0, nh1);
            if (t == myL) *(float2*)(g_xsel + b * HH + ju0) = make_float2(nh0, nh1);
        }

        // grid barrier: 4-way split counters; red (no-return) arrival at
        // ~0.854 cyc/op vs ~27 cyc/serialized atomicAdd; acquire-spin wakeup.
        __syncthreads();
        if (tid == 0) {
            asm volatile("red.release.gpu.global.add.u32 [%0], 1;"
                         :: "l"(&g_syncv[blk & 3]) : "memory");
        }
        if (tid < 4) {
            const unsigned tgt = (unsigned)(t + 1) * (NBLK / 4);
            unsigned v;
            do {
                asm volatile("ld.acquire.gpu.u32 %0, [%1];"
                             : "=r"(v) : "l"(&g_syncv[tid]));
            } while (v < tgt);
        }
        __syncthreads();
    }
}

// ---------------- K3: linear + batchnorm (+relu), one block per column -----
__global__ __launch_bounds__(128, 8)
void k_head(const float* __restrict__ w, const float* __restrict__ bias,
            const float* __restrict__ gam, const float* __restrict__ bet,
            float* __restrict__ dout, int phase)
{
    __shared__ float w_s[LEE];
    __shared__ float red[BB];
    const int n = blockIdx.x, b = threadIdx.x;
    const float* x   = phase ? g_z0 : g_xsel;
    float*       out = phase ? dout : g_z0;

    for (int k = b; k < LEE; k += BB) w_s[k] = w[(size_t)n * LEE + k];
    __syncthreads();

    float s = 0.f;
    const float* xr = x + (size_t)b * LEE;
    #pragma unroll 4
    for (int k = 0; k < LEE; k += 4) {
        float4 xv = *(const float4*)(xr + k);
        float4 wv = *(const float4*)(w_s + k);
        s += xv.x * wv.x + xv.y * wv.y + xv.z * wv.z + xv.w * wv.w;
    }
    s += bias[n];

    red[b] = s; __syncthreads();
    #pragma unroll
    for (int off = 64; off > 0; off >>= 1) {
        if (b < off) red[b] += red[b + off];
        __syncthreads();
    }
    const float mean = red[0] * (1.f / BB);
    __syncthreads();
    const float d = s - mean;
    red[b] = d * d; __syncthreads();
    #pragma unroll
    for (int off = 64; off > 0; off >>= 1) {
        if (b < off) red[b] += red[b + off];
        __syncthreads();
    }
    const float var = red[0] * (1.f / BB);

    float y = d * rsqrtf(var + EPSV) * gam[n] + bet[n];
    if (!phase) y = fmaxf(y, 0.f);
    out[(size_t)b * LEE + n] = y;
}

// ------------------------------ launcher -----------------------------------
extern "C" void kernel_launch(void* const* d_in, const int* in_sizes, int n_in,
                              void* d_out, int out_size)
{
    const int*   label    = (const int*)  d_in[0];
    const int*   llen     = (const int*)  d_in[1];
    const float* embed_w  = (const float*)d_in[2];
    const float* i2h_w    = (const float*)d_in[3];
    const float* i2h_b    = (const float*)d_in[4];
    const float* h2h_w    = (const float*)d_in[5];
    const float* h2h_b    = (const float*)d_in[6];
    const float* lin0_w   = (const float*)d_in[7];
    const float* lin0_b   = (const float*)d_in[8];
    const float* bn0_g    = (const float*)d_in[9];
    const float* bn0_b    = (const float*)d_in[10];
    const float* lin1_w   = (const float*)d_in[11];
    const float* lin1_b   = (const float*)d_in[12];
    const float* bn1_g    = (const float*)d_in[13];
    const float* bn1_b    = (const float*)d_in[14];
    float*       out      = (float*)d_out;

    const int smem_lstm = (20 * HH + 2 * 16 * BB * 4) * (int)sizeof(float); // 104 KB
    static int attr_done = 0;
    if (!attr_done) {
        cudaFuncSetAttribute(k_lstm, cudaFuncAttributeMaxDynamicSharedMemorySize,
                             smem_lstm);
        attr_done = 1;
    }

    // two no-op launches shift the ncu -s 5 -c 1 window off k_head and onto
    // k_pre / k_lstm for the next profile round
    k_nop<<<1, 32>>>();
    k_nop<<<1, 32>>>();
    k_init<<<256, 256>>>(llen);
    k_pre<<<dim3(G5 / 128, (TT * BB) / 128), 256>>>(label, embed_w, i2h_w, i2h_b);
    k_lstm<<<NBLK, 256, smem_lstm>>>(h2h_w, h2h_b);
    k_head<<<LEE, BB>>>(lin0_w, lin0_b, bn0_g, bn0_b, out, 0);
    k_head<<<LEE, BB>>>(lin1_w, lin1_b, bn1_g, bn1_b, out, 1);
}

// round 12
// speedup vs baseline: 1.6832x; 1.6832x over previous
#include <cuda_runtime.h>
#include <cstdint>
#include <cstddef>

#define TT   512
#define BB   128
#define EE   512
#define HH   512
#define G5   2560
#define LEE  512
#define EPSV 1e-5f
#define NBLK 128      // LSTM persistent blocks (1 per SM, co-resident)
#define UB   8        // units per LSTM block
#define SBL  64       // slots per LSTM block
#define CKL  128      // LSTM k-chunk

// ------------------------- static device scratch ---------------------------
__device__ float    g_pre[(size_t)TT * BB * G5];   // [t*128+b][2560]
__device__ float    g_hbuf[3][BB * HH];            // rotating hidden (SLOT space)
__device__ float    g_xsel[BB * HH];               // outs[label_len[b], b] (real b)
__device__ float    g_z0[BB * LEE];
__device__ unsigned g_sync;
__device__ int      g_slot2b[BB];                  // slot (=rank) -> real batch
__device__ int      g_Lslot[BB];                   // slot -> label_len (ascending)
__device__ int      g_maxL;

// ------------------- packed f32x2 FMA (sm_103a FFMA2) ----------------------
union F2U { float2 f; unsigned long long u; };
struct F4v { F2U lo, hi; };   // 16B = two f32x2 lanes
__device__ __forceinline__ void ffma2(F2U& acc, F2U a, F2U b) {
    asm("fma.rn.f32x2 %0, %1, %2, %0;" : "+l"(acc.u) : "l"(a.u), "l"(b.u));
}
__device__ __forceinline__ float sgm(float x) { return 1.f / (1.f + __expf(-x)); }
__device__ __forceinline__ float tanh_fast(float x) {
    return 1.f - 2.f / (1.f + __expf(2.f * x));
}

// ------------------ profiling-alignment no-op launch -----------------------
__global__ void k_nop() {}

// --------------------------- init + length sort ----------------------------
__global__ void k_init(const int* __restrict__ llen) {
    int i = blockIdx.x * blockDim.x + threadIdx.x;
    if (i < BB * HH) g_hbuf[0][i] = 0.f;
    if (blockIdx.x == 0) {
        if (threadIdx.x == 0) g_sync = 0u;
        if (threadIdx.x < BB) {
            int b  = threadIdx.x;
            int Lb = llen[b];
            int r = 0, mx = 0;
            #pragma unroll 4
            for (int j = 0; j < BB; j++) {
                int Lj = llen[j];
                r  += (Lj < Lb) || (Lj == Lb && j < b);
                mx  = max(mx, Lj);
            }
            g_slot2b[r] = b;      // slot == stable rank (ascending L)
            g_Lslot[r]  = Lb;
            if (threadIdx.x == 0) g_maxL = mx;
        }
    }
}

// ---------------- K1: pre = gather(embed) @ i2h_w^T + i2h_b ----------------
// (unchanged from R10 — profiled at 69.4% fma pipe)
__global__ __launch_bounds__(256, 2)
void k_pre(const int* __restrict__ label, const float* __restrict__ embed_w,
           const float* __restrict__ i2h_w, const float* __restrict__ i2h_b)
{
    __shared__ __align__(16) float As[2][16][128];
    __shared__ __align__(16) float Ws[2][16][128];

    const int tid = threadIdx.x;
    const int tx = tid & 15, ty = tid >> 4;
    const int n0 = blockIdx.x * 128, m0 = blockIdx.y * 128;
    const int ml = tid >> 1, lk = (tid & 1) * 8;

    const int m = m0 + ml, t_ = m >> 7, b_ = m & 127;
    const float* arow = embed_w + (size_t)label[b_ * TT + t_] * EE;
    const float* wrow = i2h_w + (size_t)(n0 + ml) * EE;

    F2U acc[8][4];
    #pragma unroll
    for (int i = 0; i < 8; i++)
        #pragma unroll
        for (int j = 0; j < 4; j++) acc[i][j].u = 0ull;

    float4 ra0 = *(const float4*)(arow + lk);
    float4 ra1 = *(const float4*)(arow + lk + 4);
    float4 rw0 = *(const float4*)(wrow + lk);
    float4 rw1 = *(const float4*)(wrow + lk + 4);

    #pragma unroll 1
    for (int ko = 0; ko < EE / 16; ++ko) {
        const int buf = ko & 1;
        As[buf][lk + 0][ml] = ra0.x; As[buf][lk + 1][ml] = ra0.y;
        As[buf][lk + 2][ml] = ra0.z; As[buf][lk + 3][ml] = ra0.w;
        As[buf][lk + 4][ml] = ra1.x; As[buf][lk + 5][ml] = ra1.y;
        As[buf][lk + 6][ml] = ra1.z; As[buf][lk + 7][ml] = ra1.w;
        Ws[buf][lk + 0][ml] = rw0.x; Ws[buf][lk + 1][ml] = rw0.y;
        Ws[buf][lk + 2][ml] = rw0.z; Ws[buf][lk + 3][ml] = rw0.w;
        Ws[buf][lk + 4][ml] = rw1.x; Ws[buf][lk + 5][ml] = rw1.y;
        Ws[buf][lk + 6][ml] = rw1.z; Ws[buf][lk + 7][ml] = rw1.w;
        __syncthreads();
        if (ko + 1 < EE / 16) {
            const int kb = (ko + 1) * 16 + lk;
            ra0 = *(const float4*)(arow + kb);
            ra1 = *(const float4*)(arow + kb + 4);
            rw0 = *(const float4*)(wrow + kb);
            rw1 = *(const float4*)(wrow + kb + 4);
        }
        #pragma unroll
        for (int k = 0; k < 16; ++k) {
            float4 aA = *(const float4*)&As[buf][k][ty * 8];       // broadcast
            float4 aB = *(const float4*)&As[buf][k][ty * 8 + 4];   // broadcast
            F4v bA = *(const F4v*)&Ws[buf][k][tx * 4];             // conflict-free
            F4v bB = *(const F4v*)&Ws[buf][k][64 + tx * 4];        // conflict-free
            float av[8] = {aA.x, aA.y, aA.z, aA.w, aB.x, aB.y, aB.z, aB.w};
            #pragma unroll
            for (int i = 0; i < 8; i++) {
                F2U ad; ad.f.x = av[i]; ad.f.y = av[i];
                ffma2(acc[i][0], ad, bA.lo);
                ffma2(acc[i][1], ad, bA.hi);
                ffma2(acc[i][2], ad, bB.lo);
                ffma2(acc[i][3], ad, bB.hi);
            }
        }
    }

    const float4 bi0 = *(const float4*)(i2h_b + n0 + tx * 4);
    const float4 bi1 = *(const float4*)(i2h_b + n0 + 64 + tx * 4);
    #pragma unroll
    for (int i = 0; i < 8; i++) {
        const int mrow = m0 + ty * 8 + i;
        float* op = g_pre + (size_t)mrow * G5 + n0 + tx * 4;
        float4 o0, o1;
        o0.x = acc[i][0].f.x + bi0.x; o0.y = acc[i][0].f.y + bi0.y;
        o0.z = acc[i][1].f.x + bi0.z; o0.w = acc[i][1].f.y + bi0.w;
        o1.x = acc[i][2].f.x + bi1.x; o1.y = acc[i][2].f.y + bi1.y;
        o1.z = acc[i][3].f.x + bi1.z; o1.w = acc[i][3].f.y + bi1.w;
        *(float4*)op        = o0;
        *(float4*)(op + 64) = o1;
    }
}

// ------------------------- K2: persistent LSTM -----------------------------
// 128 blocks = 64 unit-groups (8 units) x 2 slot-groups (64 slots).
// Thread (u = tid>>5, bp = tid&31) computes unit ju for slots sg*64+bp and
// sg*64+bp+32 (slot == length-sorted rank). Early exit is taken at WARP
// granularity via __any_sync (uniform branches); per-lane retirement only
// predicates loads/stores. Cell state in registers across the whole scan.
__global__ __launch_bounds__(256, 1)
void k_lstm(const float* __restrict__ h2h_w, const float* __restrict__ h2h_b)
{
    extern __shared__ float sm[];
    float* w_s = sm;                       // [40][512]  rows r = g*8 + u
    float* h_s = sm + 40 * HH;             // [2][32][64][4] double-buffered

    const int tid = threadIdx.x;
    const int u   = tid >> 5;              // 0..7 unit within block
    const int bp  = tid & 31;
    const int blk = blockIdx.x;
    const int ug  = blk >> 1;              // 0..63
    const int sg  = blk & 1;               // 0..1
    const int ju  = ug * UB + u;           // global unit
    const int s0l = bp, s1l = bp + 32;     // local slots
    const int s0  = sg * SBL + s0l;        // global slot (= rank)
    const int s1  = sg * SBL + s1l;

    // resident weights: 40 rows x 512 = 80 KB
    for (int i = tid; i < 40 * HH / 4; i += 256) {
        int r = i / (HH / 4), k4 = i % (HH / 4);
        int g = r >> 3, uu = r & 7;
        *(float4*)(w_s + r * HH + k4 * 4) =
            *(const float4*)(h2h_w + (size_t)(g * HH + ug * UB + uu) * HH + k4 * 4);
    }

    float bias[5];
    #pragma unroll
    for (int g = 0; g < 5; g++) bias[g] = h2h_b[g * HH + ju];

    const int bA = g_slot2b[s0], bB = g_slot2b[s1];
    const int LA = g_Lslot[s0],  LB = g_Lslot[s1];   // LB >= LA (ranks ascend)
    const int maxT = g_maxL;

    // stager mapping: thread stages 32 k of local row ls per chunk
    const int ls = tid >> 2, lh = tid & 3;
    const int Lrow = g_Lslot[sg * SBL + ls];

    float cA = 0.f, cB = 0.f;
    __syncthreads();

    #pragma unroll 1
    for (int t = 0; t <= maxT; ++t) {
        const float* hcur = g_hbuf[t % 3];
        float*       hnxt = g_hbuf[(t + 1) % 3];
        const bool actA = (t <= LA), actB = (t <= LB);
        const bool stg  = (t <= Lrow);
        const bool anyA = __any_sync(0xffffffffu, actA);
        const bool anyB = __any_sync(0xffffffffu, actB);

        F2U accA[5], accB[5];
        #pragma unroll
        for (int g = 0; g < 5; g++) { accA[g].u = 0ull; accB[g].u = 0ull; }

        float pvA[5], pvB[5];
        #pragma unroll
        for (int g = 0; g < 5; g++) { pvA[g] = 0.f; pvB[g] = 0.f; }
        if (actA) {
            #pragma unroll
            for (int g = 0; g < 5; g++)
                pvA[g] = __ldg(&g_pre[((size_t)t * BB + bA) * G5 + g * HH + ju]);
        }
        if (actB) {
            #pragma unroll
            for (int g = 0; g < 5; g++)
                pvB[g] = __ldg(&g_pre[((size_t)t * BB + bB) * G5 + g * HH + ju]);
        }

        // prefetch chunk 0 of staged row (L2 path: peers' h writes)
        float4 rg[8];
        if (stg) {
            const float* src = hcur + (sg * SBL + ls) * HH + lh * 32;
            #pragma unroll
            for (int q = 0; q < 8; q++) rg[q] = __ldcg((const float4*)(src + q * 4));
        }

        #pragma unroll 1
        for (int ch = 0; ch < HH / CKL; ++ch) {        // 4 chunks
            float* hb = h_s + (ch & 1) * (32 * SBL * 4);
            if (stg) {
                #pragma unroll
                for (int q = 0; q < 8; q++)   // h_s[k4 = lh*8+q][ls][0..3]
                    *(float4*)(hb + ((lh * 8 + q) * SBL + ls) * 4) = rg[q];
            }
            __syncthreads();                           // single sync (dbl buffer)
            if (stg && ch + 1 < HH / CKL) {
                const float* src = hcur + (sg * SBL + ls) * HH
                                   + (ch + 1) * CKL + lh * 32;
                #pragma unroll
                for (int q = 0; q < 8; q++) rg[q] = __ldcg((const float4*)(src + q * 4));
            }
            if (anyB) {
                const F4v* hp = (const F4v*)hb;
                const float* wbase = w_s + ch * CKL;
                if (anyA) {
                    #pragma unroll 4
                    for (int kq = 0; kq < CKL / 4; ++kq) {       // 32
                        F4v hA_ = hp[kq * SBL + s0l];   // conflict-free
                        F4v hB_ = hp[kq * SBL + s1l];   // conflict-free
                        #pragma unroll
                        for (int g = 0; g < 5; g++) {
                            F4v wv = *(const F4v*)(wbase
                                     + (size_t)(g * UB + u) * HH + kq * 4); // bcast
                            ffma2(accA[g], hA_.lo, wv.lo);
                            ffma2(accA[g], hA_.hi, wv.hi);
                            ffma2(accB[g], hB_.lo, wv.lo);
                            ffma2(accB[g], hB_.hi, wv.hi);
                        }
                    }
                } else {
                    #pragma unroll 4
                    for (int kq = 0; kq < CKL / 4; ++kq) {
                        F4v hB_ = hp[kq * SBL + s1l];
                        #pragma unroll
                        for (int g = 0; g < 5; g++) {
                            F4v wv = *(const F4v*)(wbase
                                     + (size_t)(g * UB + u) * HH + kq * 4);
                            ffma2(accB[g], hB_.lo, wv.lo);
                            ffma2(accB[g], hB_.hi, wv.hi);
                        }
                    }
                }
            }
        }

        if (actB) {
            float s[5];
            #pragma unroll
            for (int g = 0; g < 5; g++)
                s[g] = accB[g].f.x + accB[g].f.y + bias[g] + pvB[g];
            float ig = sgm(s[0]), fg = sgm(s[1]), og = sgm(s[2]);
            float av = fmaxf(s[3], s[4]);
            cB = fg * cB + ig * av;
            float nh = og * tanh_fast(cB);
            hnxt[s1 * HH + ju] = nh;
            if (t == LB) g_xsel[bB * HH + ju] = nh;
        }
        if (actA) {
            float s[5];
            #pragma unroll
            for (int g = 0; g < 5; g++)
                s[g] = accA[g].f.x + accA[g].f.y + bias[g] + pvA[g];
            float ig = sgm(s[0]), fg = sgm(s[1]), og = sgm(s[2]);
            float av = fmaxf(s[3], s[4]);
            cA = fg * cA + ig * av;
            float nh = og * tanh_fast(cA);
            hnxt[s0 * HH + ju] = nh;
            if (t == LA) g_xsel[bA * HH + ju] = nh;
        }

        // grid barrier: RED arrival (no-return, ~0.854 cyc/op) + acquire spin
        __syncthreads();
        if (tid == 0) {
            asm volatile("red.release.gpu.global.add.u32 [%0], 1;"
                         :: "l"(&g_sync) : "memory");
            const unsigned tgt = (unsigned)(t + 1) * NBLK;
            unsigned v;
            do {
                asm volatile("ld.acquire.gpu.u32 %0, [%1];"
                             : "=r"(v) : "l"(&g_sync));
            } while (v < tgt);
        }
        __syncthreads();
    }
}

// ---------------- K3: linear + batchnorm (+relu), one block per column -----
__global__ __launch_bounds__(128, 8)
void k_head(const float* __restrict__ w, const float* __restrict__ bias,
            const float* __restrict__ gam, const float* __restrict__ bet,
            float* __restrict__ dout, int phase)
{
    __shared__ float w_s[LEE];
    __shared__ float red[BB];
    const int n = blockIdx.x, b = threadIdx.x;
    const float* x   = phase ? g_z0 : g_xsel;
    float*       out = phase ? dout : g_z0;

    for (int k = b; k < LEE; k += BB) w_s[k] = w[(size_t)n * LEE + k];
    __syncthreads();

    float s = 0.f;
    const float* xr = x + (size_t)b * LEE;
    #pragma unroll 4
    for (int k = 0; k < LEE; k += 4) {
        float4 xv = *(const float4*)(xr + k);
        float4 wv = *(const float4*)(w_s + k);
        s += xv.x * wv.x + xv.y * wv.y + xv.z * wv.z + xv.w * wv.w;
    }
    s += bias[n];

    red[b] = s; __syncthreads();
    #pragma unroll
    for (int off = 64; off > 0; off >>= 1) {
        if (b < off) red[b] += red[b + off];
        __syncthreads();
    }
    const float mean = red[0] * (1.f / BB);
    __syncthreads();
    const float d = s - mean;
    red[b] = d * d; __syncthreads();
    #pragma unroll
    for (int off = 64; off > 0; off >>= 1) {
        if (b < off) red[b] += red[b + off];
        __syncthreads();
    }
    const float var = red[0] * (1.f / BB);

    float y = d * rsqrtf(var + EPSV) * gam[n] + bet[n];
    if (!phase) y = fmaxf(y, 0.f);
    out[(size_t)b * LEE + n] = y;
}

// ------------------------------ launcher -----------------------------------
extern "C" void kernel_launch(void* const* d_in, const int* in_sizes, int n_in,
                              void* d_out, int out_size)
{
    const int*   label    = (const int*)  d_in[0];
    const int*   llen     = (const int*)  d_in[1];
    const float* embed_w  = (const float*)d_in[2];
    const float* i2h_w    = (const float*)d_in[3];
    const float* i2h_b    = (const float*)d_in[4];
    const float* h2h_w    = (const float*)d_in[5];
    const float* h2h_b    = (const float*)d_in[6];
    const float* lin0_w   = (const float*)d_in[7];
    const float* lin0_b   = (const float*)d_in[8];
    const float* bn0_g    = (const float*)d_in[9];
    const float* bn0_b    = (const float*)d_in[10];
    const float* lin1_w   = (const float*)d_in[11];
    const float* lin1_b   = (const float*)d_in[12];
    const float* bn1_g    = (const float*)d_in[13];
    const float* bn1_b    = (const float*)d_in[14];
    float*       out      = (float*)d_out;

    const int smem_lstm = (40 * HH + 2 * 32 * SBL * 4) * (int)sizeof(float); // 144KB
    static int attr_done = 0;
    if (!attr_done) {
        cudaFuncSetAttribute(k_lstm, cudaFuncAttributeMaxDynamicSharedMemorySize,
                             smem_lstm);
        attr_done = 1;
    }

    // launch order puts k_lstm at position 4 (the slot ncu empirically captures)
    k_init<<<256, 256>>>(llen);
    k_pre<<<dim3(G5 / 128, (TT * BB) / 128), 256>>>(label, embed_w, i2h_w, i2h_b);
    k_nop<<<1, 32>>>();
    k_lstm<<<NBLK, 256, smem_lstm>>>(h2h_w, h2h_b);
    k_head<<<LEE, BB>>>(lin0_w, lin0_b, bn0_g, bn0_b, out, 0);
    k_head<<<LEE, BB>>>(lin1_w, lin1_b, bn1_g, bn1_b, out, 1);
}